// round 9
// baseline (speedup 1.0000x reference)
#include <cuda_runtime.h>
#include <cuda_bf16.h>
#include <math.h>
#include <stdint.h>

#define BB 8
#define DM 512
#define LL 4096
#define N2C 32

typedef unsigned long long u64;
typedef unsigned int u32;

union F2 { u64 u; float2 f; };

__device__ __forceinline__ u64 fma2(u64 a, u64 b, u64 c) {
    u64 d; asm("fma.rn.f32x2 %0, %1, %2, %3;" : "=l"(d) : "l"(a), "l"(b), "l"(c)); return d;
}
__device__ __forceinline__ u64 mul2(u64 a, u64 b) {
    u64 d; asm("mul.rn.f32x2 %0, %1, %2;" : "=l"(d) : "l"(a), "l"(b)); return d;
}
__device__ __forceinline__ u64 pack2(float lo, float hi) {
    u64 d; asm("mov.b64 %0, {%1, %2};" : "=l"(d) : "f"(lo), "f"(hi)); return d;
}

// ---------------- scratch (__device__ globals; no allocs allowed) ----------------
__device__ float g_h[(size_t)BB * DM * LL];              // residual (B,D,L)
__device__ float g_y[(size_t)BB * DM * LL];              // S4D+gelu output
__device__ float g_p[(size_t)BB * 2 * DM * LL];          // GEMM preactivations
__device__ __nv_bfloat16 g_whi[(size_t)4 * 2 * DM * DM]; // W split hi
__device__ __nv_bfloat16 g_wlo[(size_t)4 * 2 * DM * DM]; // W split lo
__device__ float g_hm[BB * DM];

// ================= warp-MMA primitive (baseline ISA, OK on plain sm_103) ====
__device__ __forceinline__ void mma16816(float* d, const u32* a, const u32* b) {
    asm volatile("mma.sync.aligned.m16n8k16.row.col.f32.bf16.bf16.f32 "
        "{%0,%1,%2,%3}, {%4,%5,%6,%7}, {%8,%9}, {%0,%1,%2,%3};"
        : "+f"(d[0]), "+f"(d[1]), "+f"(d[2]), "+f"(d[3])
        : "r"(a[0]), "r"(a[1]), "r"(a[2]), "r"(a[3]), "r"(b[0]), "r"(b[1]));
}

// ================= W split (all 4 layers, once per launch) =================
__global__ void wsplit_kernel(const float* __restrict__ W)
{
    int i = blockIdx.x * 256 + threadIdx.x;     // 4*1024*512 = 2M elements
    float w = W[i];
    __nv_bfloat16 h = __float2bfloat16_rn(w);
    g_whi[i] = h;
    g_wlo[i] = __float2bfloat16_rn(w - __bfloat162float(h));
}

// ================= input projection + positional embedding =================
__global__ void proj_kernel(const float* __restrict__ x,
                            const float* __restrict__ Wp,
                            const float* __restrict__ bp,
                            const float* __restrict__ pos)
{
    __shared__ float P[32][33];
    int lx = threadIdx.x, ty = threadIdx.y;
    int l0 = blockIdx.x * 32, d0 = blockIdx.y * 32, b = blockIdx.z;
    #pragma unroll
    for (int r = 0; r < 4; r++) {
        int ll = ty + r * 8;
        P[ll][lx] = pos[(size_t)(l0 + ll) * DM + d0 + lx];
    }
    __syncthreads();
    int l = l0 + lx;
    float x0 = x[(size_t)(b * 3 + 0) * LL + l];
    float x1 = x[(size_t)(b * 3 + 1) * LL + l];
    float x2 = x[(size_t)(b * 3 + 2) * LL + l];
    #pragma unroll
    for (int r = 0; r < 4; r++) {
        int dl = ty * 4 + r;
        int d = d0 + dl;
        float v = Wp[d * 3 + 0] * x0 + Wp[d * 3 + 1] * x1 + Wp[d * 3 + 2] * x2
                + bp[d] + P[lx][dl];
        g_h[(size_t)(b * DM + d) * LL + l] = v;
    }
}

// ================= S4D scan + Dskip + exact GELU (unchanged, passing) =======
__global__ __launch_bounds__(128) void ssm_kernel(
    const float* __restrict__ log_dt,
    const float* __restrict__ log_A_real,
    const float* __restrict__ A_imag,
    const float* __restrict__ C_re,
    const float* __restrict__ C_im,
    const float* __restrict__ Dskip)
{
    int tid  = blockIdx.x * blockDim.x + threadIdx.x;
    int w    = tid >> 5;
    int lane = tid & 31;
    int g    = lane >> 4;
    int sub  = lane & 15;
    int b    = w >> 8;
    int hch  = (w & 255) * 2 + g;

    float dt  = expf(log_dt[hch]);
    float Dsk = Dskip[hch];

    float wrv[2], wiv[2], Ccrv[2], nCciv[2];
    #pragma unroll
    for (int j = 0; j < 2; j++) {
        int n   = sub + 16 * j;
        int idx = hch * N2C + n;
        float Are = -expf(log_A_real[idx]);
        float Aim = A_imag[idx];
        float dr = Are * dt, di = Aim * dt;
        float er = expf(dr);
        float wrr = er * cosf(di), wii = er * sinf(di);
        float nr = wrr - 1.0f, ni = wii;
        float inv = 1.0f / (Are * Are + Aim * Aim);
        float qr = (nr * Are + ni * Aim) * inv;
        float qi = (ni * Are - nr * Aim) * inv;
        float cr = C_re[idx], ci = C_im[idx];
        wrv[j] = wrr; wiv[j] = wii;
        Ccrv[j]  =  2.0f * (cr * qr - ci * qi);
        nCciv[j] = -2.0f * (cr * qi + ci * qr);
    }
    u64 wr2   = pack2(wrv[0],  wrv[1]);
    u64 wi2   = pack2(wiv[0],  wiv[1]);
    u64 nwi2  = pack2(-wiv[0], -wiv[1]);
    u64 Ccr2  = pack2(Ccrv[0], Ccrv[1]);
    u64 nCci2 = pack2(nCciv[0], nCciv[1]);

    const float* up = g_h + (size_t)(b * DM + hch) * LL;
    float*       yp = g_y + (size_t)(b * DM + hch) * LL;

    u64 sr2 = 0ull, si2 = 0ull;
    float4 uv[4], nv[4];
    #pragma unroll
    for (int q = 0; q < 4; q++) uv[q] = *(const float4*)(up + q * 4);

    for (int c = 0; c < LL / 16; c++) {
        if (c + 1 < LL / 16) {
            #pragma unroll
            for (int q = 0; q < 4; q++)
                nv[q] = *(const float4*)(up + (c + 1) * 16 + q * 4);
        }
        float yown = 0.f, uown = 0.f;
        #pragma unroll
        for (int t = 0; t < 16; t++) {
            float ut;
            {
                float4 vq = uv[t >> 2];
                int cc = t & 3;
                ut = (cc == 0) ? vq.x : (cc == 1) ? vq.y : (cc == 2) ? vq.z : vq.w;
            }
            u64 ut2 = pack2(ut, ut);
            u64 a2  = fma2(nwi2, si2, ut2);
            u64 b2  = fma2(wr2, si2, mul2(wi2, sr2));
            sr2 = fma2(wr2, sr2, a2);
            si2 = b2;
            F2 cvp; cvp.u = fma2(nCci2, si2, mul2(Ccr2, sr2));
            float cv = cvp.f.x + cvp.f.y;
            cv += __shfl_xor_sync(0xffffffffu, cv, 8);
            cv += __shfl_xor_sync(0xffffffffu, cv, 4);
            cv += __shfl_xor_sync(0xffffffffu, cv, 2);
            cv += __shfl_xor_sync(0xffffffffu, cv, 1);
            if (sub == t) { yown = cv; uown = ut; }
        }
        float v   = fmaf(Dsk, uown, yown);
        float gel = 0.5f * v * (1.0f + erff(v * 0.70710678118654752f));
        yp[c * 16 + sub] = gel;
        #pragma unroll
        for (int q = 0; q < 4; q++) uv[q] = nv[q];
    }
}

// ================= bf16-split warp-MMA GEMM (explicit-address fragments) ====
// P[b,m,l] = sum_k W[m,k] Y[b,k,l] + bias[m]; bf16 hi/lo split, 3 mma passes
// (hi*hi + lo*hi + hi*lo) accumulated fp32. CTA 128m x 128n x K32; 8 warps 2x4.
// W pointers are computed INSIDE the kernel from the layer index — device
// globals must never appear in host-side pointer arithmetic (R7/R8 bug: the
// host-shadow address silently reads zeros via ATS on GB300).
#define BKC 32
#define KSTEPS (DM / BKC)    // 16
#define ASTR 144             // smem row stride in bytes (hi [0,64), lo [64,128))

__global__ __launch_bounds__(256) void gemm_mma_kernel(
    int layer,
    const float* __restrict__ bias)          // + layer*1024 (host-side, real input ptr)
{
    __shared__ __align__(16) char smA[128 * ASTR];   // 18 KB
    __shared__ __align__(16) char smB[128 * ASTR];   // 18 KB

    int tid = threadIdx.x;
    int lane = tid & 31, warp = tid >> 5;
    int grp = lane >> 2, tig = lane & 3;
    int wm = warp & 1, wn = warp >> 1;
    int m0 = blockIdx.x * 128;
    int n0 = blockIdx.y * 128;
    int bz = blockIdx.z;

    const __nv_bfloat16* whi_t = g_whi + (size_t)layer * 2 * DM * DM + (size_t)m0 * DM;
    const __nv_bfloat16* wlo_t = g_wlo + (size_t)layer * 2 * DM * DM + (size_t)m0 * DM;
    const float* Ybase = g_y + (size_t)bz * DM * LL + n0;

    float acc[4][4][4];
    #pragma unroll
    for (int i = 0; i < 4; i++)
        #pragma unroll
        for (int j = 0; j < 4; j++)
            #pragma unroll
            for (int q = 0; q < 4; q++) acc[i][j][q] = 0.f;

    // staging thread roles
    int arow = tid >> 3;            // 0..31 (x4 -> 128 m rows)
    int aseg = tid & 7;             // 0-3 hi segs, 4-7 lo segs
    int asplit = aseg >> 2;
    int akoff = (aseg & 3) * 8;     // element offset within K32
    int nq  = tid & 31;             // n quad
    int kkb = tid >> 5;             // 0..7 -> k-pairs kkb, kkb+8

    uint4  rA[4];
    float4 rY[2][2];
    const __nv_bfloat16* wsrc = asplit ? wlo_t : whi_t;

    // ---- prologue: load + store chunk 0 ----
    #pragma unroll
    for (int i = 0; i < 4; i++)
        rA[i] = *(const uint4*)(wsrc + (size_t)(arow + 32 * i) * DM + akoff);
    #pragma unroll
    for (int p = 0; p < 2; p++) {
        int k = 2 * (kkb + 8 * p);
        rY[p][0] = *(const float4*)(Ybase + (size_t)k * LL + 4 * nq);
        rY[p][1] = *(const float4*)(Ybase + (size_t)(k + 1) * LL + 4 * nq);
    }
    #pragma unroll
    for (int i = 0; i < 4; i++)
        *(uint4*)(smA + (arow + 32 * i) * ASTR + asplit * 64 + (aseg & 3) * 16) = rA[i];
    #pragma unroll
    for (int p = 0; p < 2; p++) {
        int pr = kkb + 8 * p;
        float a0v[4] = {rY[p][0].x, rY[p][0].y, rY[p][0].z, rY[p][0].w};
        float a1v[4] = {rY[p][1].x, rY[p][1].y, rY[p][1].z, rY[p][1].w};
        #pragma unroll
        for (int j = 0; j < 4; j++) {
            int n = 4 * nq + j;
            __nv_bfloat16 h0 = __float2bfloat16_rn(a0v[j]);
            __nv_bfloat16 h1 = __float2bfloat16_rn(a1v[j]);
            __nv_bfloat162 hv; hv.x = h0; hv.y = h1;
            *(u32*)(smB + n * ASTR + 4 * pr) = *(u32*)&hv;
            __nv_bfloat162 lv;
            lv.x = __float2bfloat16_rn(a0v[j] - __bfloat162float(h0));
            lv.y = __float2bfloat16_rn(a1v[j] - __bfloat162float(h1));
            *(u32*)(smB + n * ASTR + 64 + 4 * pr) = *(u32*)&lv;
        }
    }
    __syncthreads();

    for (int c = 0; c < KSTEPS; c++) {
        if (c + 1 < KSTEPS) {      // register prefetch of next chunk
            int k0 = (c + 1) * BKC;
            #pragma unroll
            for (int i = 0; i < 4; i++)
                rA[i] = *(const uint4*)(wsrc + (size_t)(arow + 32 * i) * DM + k0 + akoff);
            #pragma unroll
            for (int p = 0; p < 2; p++) {
                int k = 2 * (kkb + 8 * p);
                rY[p][0] = *(const float4*)(Ybase + (size_t)(k0 + k) * LL + 4 * nq);
                rY[p][1] = *(const float4*)(Ybase + (size_t)(k0 + k + 1) * LL + 4 * nq);
            }
        }
        // ---- MMA on smem chunk c: fragments via explicit LDS.32 ----
        #pragma unroll
        for (int kk = 0; kk < 2; kk++) {
            u32 afh[4][4], afl[4][4], bfh[4][2], bfl[4][2];
            #pragma unroll
            for (int mt = 0; mt < 4; mt++) {
                const char* ab = smA + (wm * 64 + mt * 16 + grp) * ASTR + kk * 32 + tig * 4;
                afh[mt][0] = *(const u32*)(ab);                  // A[m][2t,2t+1]
                afh[mt][1] = *(const u32*)(ab + 8 * ASTR);       // A[m+8][2t..]
                afh[mt][2] = *(const u32*)(ab + 16);             // A[m][2t+8..]
                afh[mt][3] = *(const u32*)(ab + 8 * ASTR + 16);  // A[m+8][2t+8..]
                afl[mt][0] = *(const u32*)(ab + 64);
                afl[mt][1] = *(const u32*)(ab + 8 * ASTR + 64);
                afl[mt][2] = *(const u32*)(ab + 80);
                afl[mt][3] = *(const u32*)(ab + 8 * ASTR + 80);
            }
            #pragma unroll
            for (int nt = 0; nt < 4; nt++) {
                const char* bb = smB + (wn * 32 + nt * 8 + grp) * ASTR + kk * 32 + tig * 4;
                bfh[nt][0] = *(const u32*)(bb);                  // B[2t..][n]
                bfh[nt][1] = *(const u32*)(bb + 16);             // B[2t+8..][n]
                bfl[nt][0] = *(const u32*)(bb + 64);
                bfl[nt][1] = *(const u32*)(bb + 80);
            }
            #pragma unroll
            for (int mt = 0; mt < 4; mt++)
                #pragma unroll
                for (int nt = 0; nt < 4; nt++) {
                    mma16816(acc[mt][nt], afh[mt], bfh[nt]);   // hi*hi
                    mma16816(acc[mt][nt], afl[mt], bfh[nt]);   // lo*hi
                    mma16816(acc[mt][nt], afh[mt], bfl[nt]);   // hi*lo
                }
        }
        __syncthreads();
        if (c + 1 < KSTEPS) {      // store next chunk to smem
            #pragma unroll
            for (int i = 0; i < 4; i++)
                *(uint4*)(smA + (arow + 32 * i) * ASTR + asplit * 64 + (aseg & 3) * 16) = rA[i];
            #pragma unroll
            for (int p = 0; p < 2; p++) {
                int pr = kkb + 8 * p;
                float a0v[4] = {rY[p][0].x, rY[p][0].y, rY[p][0].z, rY[p][0].w};
                float a1v[4] = {rY[p][1].x, rY[p][1].y, rY[p][1].z, rY[p][1].w};
                #pragma unroll
                for (int j = 0; j < 4; j++) {
                    int n = 4 * nq + j;
                    __nv_bfloat16 h0 = __float2bfloat16_rn(a0v[j]);
                    __nv_bfloat16 h1 = __float2bfloat16_rn(a1v[j]);
                    __nv_bfloat162 hv; hv.x = h0; hv.y = h1;
                    *(u32*)(smB + n * ASTR + 4 * pr) = *(u32*)&hv;
                    __nv_bfloat162 lv;
                    lv.x = __float2bfloat16_rn(a0v[j] - __bfloat162float(h0));
                    lv.y = __float2bfloat16_rn(a1v[j] - __bfloat162float(h1));
                    *(u32*)(smB + n * ASTR + 64 + 4 * pr) = *(u32*)&lv;
                }
            }
            __syncthreads();
        }
    }

    // ---- epilogue: add bias, write preactivations ----
    float* Pp = g_p + (size_t)bz * 2 * DM * LL;
    #pragma unroll
    for (int mt = 0; mt < 4; mt++) {
        int r0 = m0 + wm * 64 + mt * 16 + grp;
        float bv0 = bias[r0];
        float bv1 = bias[r0 + 8];
        #pragma unroll
        for (int nt = 0; nt < 4; nt++) {
            int col = n0 + wn * 32 + nt * 8 + tig * 2;
            float2 v0 = {acc[mt][nt][0] + bv0, acc[mt][nt][1] + bv0};
            float2 v1 = {acc[mt][nt][2] + bv1, acc[mt][nt][3] + bv1};
            *(float2*)(Pp + (size_t)r0 * LL + col) = v0;
            *(float2*)(Pp + (size_t)(r0 + 8) * LL + col) = v1;
        }
    }
}

// ================= fused GLU + residual + LayerNorm =================
__global__ __launch_bounds__(256) void glu_ln_kernel(const float* __restrict__ gam,
                                                     const float* __restrict__ bet)
{
    int lx = threadIdx.x, ty = threadIdx.y;
    int l = blockIdx.x * 32 + lx;
    int b = blockIdx.y;
    __shared__ float R1[8][32], R2[8][32];
    size_t hbase = (size_t)b * DM * LL + l;
    size_t pbase = (size_t)b * 2 * DM * LL + l;
    float v[64];
    float s = 0.f, q = 0.f;
    #pragma unroll
    for (int r = 0; r < 64; r++) {
        int d = ty + r * 8;
        float a    = g_p[pbase + (size_t)d * LL];
        float gate = g_p[pbase + (size_t)(d + DM) * LL];
        float vv = g_h[hbase + (size_t)d * LL] + a / (1.0f + expf(-gate));
        v[r] = vv;
        s += vv; q = fmaf(vv, vv, q);
    }
    R1[ty][lx] = s; R2[ty][lx] = q;
    __syncthreads();
    if (ty == 0) {
        float S = 0.f, Q = 0.f;
        #pragma unroll
        for (int r = 0; r < 8; r++) { S += R1[r][lx]; Q += R2[r][lx]; }
        float mu = S * (1.0f / DM);
        float var = Q * (1.0f / DM) - mu * mu;
        R1[0][lx] = mu;
        R2[0][lx] = rsqrtf(var + 1e-5f);
    }
    __syncthreads();
    float mu = R1[0][lx], rs = R2[0][lx];
    #pragma unroll
    for (int r = 0; r < 64; r++) {
        int d = ty + r * 8;
        g_h[hbase + (size_t)d * LL] = (v[r] - mu) * rs * gam[d] + bet[d];
    }
}

// ================= mean over L =================
__global__ void mean_kernel()
{
    int row = blockIdx.x;
    size_t base = (size_t)row * LL;
    float s = 0.f;
    for (int l = threadIdx.x; l < LL; l += 128) s += g_h[base + l];
    #pragma unroll
    for (int o = 16; o; o >>= 1) s += __shfl_xor_sync(0xffffffffu, s, o);
    __shared__ float sm[4];
    int wid = threadIdx.x >> 5;
    if ((threadIdx.x & 31) == 0) sm[wid] = s;
    __syncthreads();
    if (threadIdx.x == 0)
        g_hm[row] = (sm[0] + sm[1] + sm[2] + sm[3]) * (1.0f / LL);
}

// ================= stats head =================
__global__ void stats_kernel(const float* __restrict__ Ws,
                             const float* __restrict__ bs,
                             float* __restrict__ out)
{
    int w = (blockIdx.x * blockDim.x + threadIdx.x) >> 5;
    int lane = threadIdx.x & 31;
    int b = w >> 9;
    int o = w & 511;
    const float* hm = g_hm + b * DM;
    const float* wrow = Ws + (size_t)o * DM;
    float s = 0.f;
    for (int d = lane; d < DM; d += 32) s = fmaf(wrow[d], hm[d], s);
    #pragma unroll
    for (int off = 16; off; off >>= 1) s += __shfl_xor_sync(0xffffffffu, s, off);
    if (lane == 0) {
        float v = s + bs[o];
        if (o < 256) out[b * 256 + o] = v;
        else         out[2048 + b * 256 + (o - 256)] = v;
    }
}

// ================= launch =================
extern "C" void kernel_launch(void* const* d_in, const int* in_sizes, int n_in,
                              void* d_out, int out_size)
{
    const float* x      = (const float*)d_in[0];
    const float* Wproj  = (const float*)d_in[1];
    const float* bproj  = (const float*)d_in[2];
    const float* pos    = (const float*)d_in[3];
    const float* log_dt = (const float*)d_in[4];
    const float* logAre = (const float*)d_in[5];
    const float* Aim    = (const float*)d_in[6];
    const float* Cre    = (const float*)d_in[7];
    const float* Cim    = (const float*)d_in[8];
    const float* Dsk    = (const float*)d_in[9];
    const float* Wout   = (const float*)d_in[10];
    const float* bout   = (const float*)d_in[11];
    const float* lng    = (const float*)d_in[12];
    const float* lnb    = (const float*)d_in[13];
    const float* Wstats = (const float*)d_in[14];
    const float* bstats = (const float*)d_in[15];
    float* out = (float*)d_out;

    wsplit_kernel<<<4 * 2 * DM * DM / 256, 256>>>(Wout);
    proj_kernel<<<dim3(LL / 32, DM / 32, BB), dim3(32, 8)>>>(x, Wproj, bproj, pos);

    for (int layer = 0; layer < 4; ++layer) {
        ssm_kernel<<<512, 128>>>(log_dt + layer * DM,
                                 logAre + (size_t)layer * DM * N2C,
                                 Aim    + (size_t)layer * DM * N2C,
                                 Cre    + (size_t)layer * DM * N2C,
                                 Cim    + (size_t)layer * DM * N2C,
                                 Dsk    + layer * DM);
        gemm_mma_kernel<<<dim3(2 * DM / 128, LL / 128, BB), 256>>>(
            layer, bout + layer * 2 * DM);
        glu_ln_kernel<<<dim3(LL / 32, BB), dim3(32, 8)>>>(lng + layer * DM,
                                                          lnb + layer * DM);
    }

    mean_kernel<<<BB * DM, 128>>>();
    stats_kernel<<<512, 256>>>(Wstats, bstats, out);
}

// round 13
// speedup vs baseline: 1.3936x; 1.3936x over previous
#include <cuda_runtime.h>
#include <cuda_bf16.h>
#include <math.h>
#include <stdint.h>

#define BB 8
#define DM 512
#define LL 4096
#define N2C 32

typedef unsigned long long u64;
typedef unsigned int u32;

union F2 { u64 u; float2 f; };

__device__ __forceinline__ u64 fma2(u64 a, u64 b, u64 c) {
    u64 d; asm("fma.rn.f32x2 %0, %1, %2, %3;" : "=l"(d) : "l"(a), "l"(b), "l"(c)); return d;
}
__device__ __forceinline__ u64 mul2(u64 a, u64 b) {
    u64 d; asm("mul.rn.f32x2 %0, %1, %2;" : "=l"(d) : "l"(a), "l"(b)); return d;
}
__device__ __forceinline__ u64 pack2(float lo, float hi) {
    u64 d; asm("mov.b64 %0, {%1, %2};" : "=l"(d) : "f"(lo), "f"(hi)); return d;
}

// ---------------- scratch (__device__ globals; no allocs allowed) ----------------
__device__ float g_h[(size_t)BB * DM * LL];                // residual (B,D,L)
__device__ __nv_bfloat16 g_yhi[(size_t)BB * DM * LL];      // S4D+gelu output, bf16 hi
__device__ __nv_bfloat16 g_ylo[(size_t)BB * DM * LL];      // S4D+gelu output, bf16 lo
__device__ float g_p[(size_t)BB * 2 * DM * LL];            // GEMM preactivations
__device__ __nv_bfloat16 g_whi[(size_t)4 * 2 * DM * DM];   // W split hi
__device__ __nv_bfloat16 g_wlo[(size_t)4 * 2 * DM * DM];   // W split lo
__device__ float g_hm[BB * DM];

// ================= warp-MMA primitives (baseline ISA, OK on plain sm_103) ===
__device__ __forceinline__ u32 smem_u32(const void* p) {
    u32 a;
    asm("{ .reg .u64 t; cvta.to.shared.u64 t, %1; cvt.u32.u64 %0, t; }" : "=r"(a) : "l"(p));
    return a;
}
__device__ __forceinline__ void mma16816(float* d, const u32* a, const u32* b) {
    asm volatile("mma.sync.aligned.m16n8k16.row.col.f32.bf16.bf16.f32 "
        "{%0,%1,%2,%3}, {%4,%5,%6,%7}, {%8,%9}, {%0,%1,%2,%3};"
        : "+f"(d[0]), "+f"(d[1]), "+f"(d[2]), "+f"(d[3])
        : "r"(a[0]), "r"(a[1]), "r"(a[2]), "r"(a[3]), "r"(b[0]), "r"(b[1]));
}
__device__ __forceinline__ void ldsm4(u32* r, u32 addr) {
    asm volatile("ldmatrix.sync.aligned.m8n8.x4.shared.b16 {%0,%1,%2,%3}, [%4];"
        : "=r"(r[0]), "=r"(r[1]), "=r"(r[2]), "=r"(r[3]) : "r"(addr));
}
__device__ __forceinline__ void ldsm4t(u32* r, u32 addr) {
    asm volatile("ldmatrix.sync.aligned.m8n8.x4.trans.shared.b16 {%0,%1,%2,%3}, [%4];"
        : "=r"(r[0]), "=r"(r[1]), "=r"(r[2]), "=r"(r[3]) : "r"(addr));
}

// ================= W split (all 4 layers, once per launch) =================
__global__ void wsplit_kernel(const float* __restrict__ W)
{
    int i = blockIdx.x * 256 + threadIdx.x;
    float w = W[i];
    __nv_bfloat16 h = __float2bfloat16_rn(w);
    g_whi[i] = h;
    g_wlo[i] = __float2bfloat16_rn(w - __bfloat162float(h));
}

// ================= input projection + positional embedding =================
__global__ void proj_kernel(const float* __restrict__ x,
                            const float* __restrict__ Wp,
                            const float* __restrict__ bp,
                            const float* __restrict__ pos)
{
    __shared__ float P[32][33];
    int lx = threadIdx.x, ty = threadIdx.y;
    int l0 = blockIdx.x * 32, d0 = blockIdx.y * 32, b = blockIdx.z;
    #pragma unroll
    for (int r = 0; r < 4; r++) {
        int ll = ty + r * 8;
        P[ll][lx] = pos[(size_t)(l0 + ll) * DM + d0 + lx];
    }
    __syncthreads();
    int l = l0 + lx;
    float x0 = x[(size_t)(b * 3 + 0) * LL + l];
    float x1 = x[(size_t)(b * 3 + 1) * LL + l];
    float x2 = x[(size_t)(b * 3 + 2) * LL + l];
    #pragma unroll
    for (int r = 0; r < 4; r++) {
        int dl = ty * 4 + r;
        int d = d0 + dl;
        float v = Wp[d * 3 + 0] * x0 + Wp[d * 3 + 1] * x1 + Wp[d * 3 + 2] * x2
                + bp[d] + P[lx][dl];
        g_h[(size_t)(b * DM + d) * LL + l] = v;
    }
}

// ================= S4D scan + Dskip + exact GELU, bf16-split output =========
// Per 16-step chunk: local per-lane accumulation into 16 packed regs, then ONE
// recursive-halving reduce-scatter (15 shfl) instead of 64 butterfly shfls.
__global__ __launch_bounds__(128) void ssm_kernel(
    const float* __restrict__ log_dt,
    const float* __restrict__ log_A_real,
    const float* __restrict__ A_imag,
    const float* __restrict__ C_re,
    const float* __restrict__ C_im,
    const float* __restrict__ Dskip)
{
    int tid  = blockIdx.x * blockDim.x + threadIdx.x;
    int w    = tid >> 5;
    int lane = tid & 31;
    int g    = lane >> 4;
    int sub  = lane & 15;
    int b    = w >> 8;
    int hch  = (w & 255) * 2 + g;

    float dt  = expf(log_dt[hch]);
    float Dsk = Dskip[hch];

    float wrv[2], wiv[2], Ccrv[2], nCciv[2];
    #pragma unroll
    for (int j = 0; j < 2; j++) {
        int n   = sub + 16 * j;
        int idx = hch * N2C + n;
        float Are = -expf(log_A_real[idx]);
        float Aim = A_imag[idx];
        float dr = Are * dt, di = Aim * dt;
        float er = expf(dr);
        float wrr = er * cosf(di), wii = er * sinf(di);
        float nr = wrr - 1.0f, ni = wii;
        float inv = 1.0f / (Are * Are + Aim * Aim);
        float qr = (nr * Are + ni * Aim) * inv;
        float qi = (ni * Are - nr * Aim) * inv;
        float cr = C_re[idx], ci = C_im[idx];
        wrv[j] = wrr; wiv[j] = wii;
        Ccrv[j]  =  2.0f * (cr * qr - ci * qi);
        nCciv[j] = -2.0f * (cr * qi + ci * qr);
    }
    u64 wr2   = pack2(wrv[0],  wrv[1]);
    u64 wi2   = pack2(wiv[0],  wiv[1]);
    u64 nwi2  = pack2(-wiv[0], -wiv[1]);
    u64 Ccr2  = pack2(Ccrv[0], Ccrv[1]);
    u64 nCci2 = pack2(nCciv[0], nCciv[1]);

    size_t rowoff = (size_t)(b * DM + hch) * LL;
    const float* up = g_h + rowoff;
    __nv_bfloat16* yhp = g_yhi + rowoff;
    __nv_bfloat16* ylp = g_ylo + rowoff;

    u64 sr2 = 0ull, si2 = 0ull;
    float4 uv[4], nv[4];
    #pragma unroll
    for (int q = 0; q < 4; q++) uv[q] = *(const float4*)(up + q * 4);

    for (int c = 0; c < LL / 16; c++) {
        if (c + 1 < LL / 16) {
            #pragma unroll
            for (int q = 0; q < 4; q++)
                nv[q] = *(const float4*)(up + (c + 1) * 16 + q * 4);
        }
        u64 y2[16];
        #pragma unroll
        for (int t = 0; t < 16; t++) y2[t] = 0ull;
        float uown = 0.f;
        #pragma unroll
        for (int t = 0; t < 16; t++) {
            float ut;
            {
                float4 vq = uv[t >> 2];
                int cc = t & 3;
                ut = (cc == 0) ? vq.x : (cc == 1) ? vq.y : (cc == 2) ? vq.z : vq.w;
            }
            u64 ut2 = pack2(ut, ut);
            u64 a2  = fma2(nwi2, si2, ut2);
            u64 b2  = fma2(wr2, si2, mul2(wi2, sr2));
            sr2 = fma2(wr2, sr2, a2);
            si2 = b2;
            y2[t] = fma2(Ccr2, sr2, y2[t]);
            y2[t] = fma2(nCci2, si2, y2[t]);
            if (sub == t) uown = ut;
        }
        // collapse packed pairs to scalars
        float a[16];
        #pragma unroll
        for (int t = 0; t < 16; t++) { F2 f; f.u = y2[t]; a[t] = f.f.x + f.f.y; }
        // recursive-halving reduce-scatter: lane sub ends with sum for t = sub
        #pragma unroll
        for (int m = 8, cnt = 16; m >= 1; m >>= 1, cnt >>= 1) {
            bool hi = (sub & m) != 0;
            #pragma unroll
            for (int i = 0; i < 8; i++) {
                if (i < cnt / 2) {
                    float send = hi ? a[i] : a[i + cnt / 2];
                    float keep = hi ? a[i + cnt / 2] : a[i];
                    a[i] = keep + __shfl_xor_sync(0xffffffffu, send, m);
                }
            }
        }
        float v   = fmaf(Dsk, uown, a[0]);
        float gel = 0.5f * v * (1.0f + erff(v * 0.70710678118654752f));
        __nv_bfloat16 h = __float2bfloat16_rn(gel);
        yhp[c * 16 + sub] = h;
        ylp[c * 16 + sub] = __float2bfloat16_rn(gel - __bfloat162float(h));
        #pragma unroll
        for (int q = 0; q < 4; q++) uv[q] = nv[q];
    }
}

// ================= bf16-split warp-MMA GEMM (ldmatrix, coalesced staging) ===
// P[b,m,l] = sum_k W[m,k] Y[b,k,l] + bias[m]; 3 passes hi*hi+lo*hi+hi*lo, fp32.
// CTA 128m x 128n x K32; 8 warps 2x4. A smem [m][k] stride 144 (validated R9),
// non-trans ldmatrix. B smem [k][n] stride 272, COALESCED stores from the
// pre-split g_yhi/g_ylo planes; ldmatrix.x4.trans does the transpose.
#define BKC 32
#define KSTEPS (DM / BKC)    // 16
#define ASTR 144
#define BSTR 272             // 128 bf16 + 16B pad; conflict-free trans-ldsm
#define SMA  0
#define SMBH (128 * ASTR)            // 18432
#define SMBL (SMBH + 32 * BSTR)      // 27136
#define SMTOT (SMBL + 32 * BSTR)     // 35840

__global__ __launch_bounds__(256) void gemm_mma_kernel(
    int layer,
    const float* __restrict__ bias)
{
    __shared__ __align__(16) char sm[SMTOT];

    int tid = threadIdx.x;
    int lane = tid & 31, warp = tid >> 5;
    int grp = lane >> 2, tig = lane & 3;
    int wm = warp & 1, wn = warp >> 1;
    int m0 = blockIdx.x * 128;
    int n0 = blockIdx.y * 128;
    int bz = blockIdx.z;

    const __nv_bfloat16* whi_t = g_whi + (size_t)layer * 2 * DM * DM + (size_t)m0 * DM;
    const __nv_bfloat16* wlo_t = g_wlo + (size_t)layer * 2 * DM * DM + (size_t)m0 * DM;
    const __nv_bfloat16* yhi_b = g_yhi + (size_t)bz * DM * LL + n0;
    const __nv_bfloat16* ylo_b = g_ylo + (size_t)bz * DM * LL + n0;

    u32 smu = smem_u32(sm);

    float acc[4][4][4];
    #pragma unroll
    for (int i = 0; i < 4; i++)
        #pragma unroll
        for (int j = 0; j < 4; j++)
            #pragma unroll
            for (int q = 0; q < 4; q++) acc[i][j][q] = 0.f;

    // staging roles
    int arow = tid >> 3;            // 0..31 (+32i)
    int aseg = tid & 7;             // 0-3 hi, 4-7 lo
    int asplit = aseg >> 2;
    int akoff = (aseg & 3) * 8;
    const __nv_bfloat16* wsrc = asplit ? wlo_t : whi_t;
    int brow = tid >> 4;            // 0..15 (+16i)
    int bseg = tid & 15;            // 16B segments across 256B row

    uint4 rA[4], rBh[2], rBl[2];

#define GLOAD(k0) do {                                                          \
        _Pragma("unroll") for (int i = 0; i < 4; i++)                           \
            rA[i] = *(const uint4*)(wsrc + (size_t)(arow + 32 * i) * DM + (k0) + akoff); \
        _Pragma("unroll") for (int i = 0; i < 2; i++) {                         \
            size_t off = (size_t)((k0) + brow + 16 * i) * LL + bseg * 8;        \
            rBh[i] = *(const uint4*)(yhi_b + off);                              \
            rBl[i] = *(const uint4*)(ylo_b + off);                              \
        }                                                                       \
    } while (0)

#define SSTORE() do {                                                           \
        _Pragma("unroll") for (int i = 0; i < 4; i++)                           \
            *(uint4*)(sm + SMA + (arow + 32 * i) * ASTR + asplit * 64 + (aseg & 3) * 16) = rA[i]; \
        _Pragma("unroll") for (int i = 0; i < 2; i++) {                         \
            *(uint4*)(sm + SMBH + (brow + 16 * i) * BSTR + bseg * 16) = rBh[i]; \
            *(uint4*)(sm + SMBL + (brow + 16 * i) * BSTR + bseg * 16) = rBl[i]; \
        }                                                                       \
    } while (0)

    GLOAD(0);
    SSTORE();
    __syncthreads();

    // ldmatrix lane address components
    int a_r = lane & 15;                              // A rows m0..15
    int a_c = (lane >> 4) << 4;                       // 0 | 16B (k half)
    int b_r = (lane & 7) + ((lane >> 3) & 1) * 8;     // B rows k0..15
    int b_c = (lane >> 4) << 4;                       // 0 | 16B (n + 8)

    for (int c = 0; c < KSTEPS; c++) {
        if (c + 1 < KSTEPS) GLOAD((c + 1) * BKC);
        #pragma unroll
        for (int kk = 0; kk < 2; kk++) {
            u32 bfh[4][2], bfl[4][2];
            #pragma unroll
            for (int t = 0; t < 2; t++) {
                u32 rr[4];
                u32 browl = (u32)(kk * 16 + b_r);
                u32 bcol  = (u32)((wn * 32 + t * 16) * 2 + b_c);
                ldsm4t(rr, smu + SMBH + browl * BSTR + bcol);
                bfh[2 * t][0] = rr[0]; bfh[2 * t][1] = rr[1];
                bfh[2 * t + 1][0] = rr[2]; bfh[2 * t + 1][1] = rr[3];
                ldsm4t(rr, smu + SMBL + browl * BSTR + bcol);
                bfl[2 * t][0] = rr[0]; bfl[2 * t][1] = rr[1];
                bfl[2 * t + 1][0] = rr[2]; bfl[2 * t + 1][1] = rr[3];
            }
            #pragma unroll
            for (int mt = 0; mt < 4; mt++) {
                u32 af[4], al[4];
                u32 arowl = (u32)(wm * 64 + mt * 16 + a_r);
                u32 acol  = (u32)(kk * 32 + a_c);
                ldsm4(af, smu + SMA + arowl * ASTR + acol);
                ldsm4(al, smu + SMA + arowl * ASTR + 64 + acol);
                #pragma unroll
                for (int nt = 0; nt < 4; nt++) {
                    mma16816(acc[mt][nt], af, bfh[nt]);   // hi*hi
                    mma16816(acc[mt][nt], al, bfh[nt]);   // lo*hi
                    mma16816(acc[mt][nt], af, bfl[nt]);   // hi*lo
                }
            }
        }
        __syncthreads();
        if (c + 1 < KSTEPS) {
            SSTORE();
            __syncthreads();
        }
    }

    // ---- epilogue: add bias, write preactivations (validated R9) ----
    float* Pp = g_p + (size_t)bz * 2 * DM * LL;
    #pragma unroll
    for (int mt = 0; mt < 4; mt++) {
        int r0 = m0 + wm * 64 + mt * 16 + grp;
        float bv0 = bias[r0];
        float bv1 = bias[r0 + 8];
        #pragma unroll
        for (int nt = 0; nt < 4; nt++) {
            int col = n0 + wn * 32 + nt * 8 + tig * 2;
            float2 v0 = {acc[mt][nt][0] + bv0, acc[mt][nt][1] + bv0};
            float2 v1 = {acc[mt][nt][2] + bv1, acc[mt][nt][3] + bv1};
            *(float2*)(Pp + (size_t)r0 * LL + col) = v0;
            *(float2*)(Pp + (size_t)(r0 + 8) * LL + col) = v1;
        }
    }
}

// ================= fused GLU + residual + LayerNorm =================
__global__ __launch_bounds__(256) void glu_ln_kernel(const float* __restrict__ gam,
                                                     const float* __restrict__ bet)
{
    int lx = threadIdx.x, ty = threadIdx.y;
    int l = blockIdx.x * 32 + lx;
    int b = blockIdx.y;
    __shared__ float R1[8][32], R2[8][32];
    size_t hbase = (size_t)b * DM * LL + l;
    size_t pbase = (size_t)b * 2 * DM * LL + l;
    float v[64];
    float s = 0.f, q = 0.f;
    #pragma unroll
    for (int r = 0; r < 64; r++) {
        int d = ty + r * 8;
        float a    = g_p[pbase + (size_t)d * LL];
        float gate = g_p[pbase + (size_t)(d + DM) * LL];
        float vv = g_h[hbase + (size_t)d * LL] + a / (1.0f + expf(-gate));
        v[r] = vv;
        s += vv; q = fmaf(vv, vv, q);
    }
    R1[ty][lx] = s; R2[ty][lx] = q;
    __syncthreads();
    if (ty == 0) {
        float S = 0.f, Q = 0.f;
        #pragma unroll
        for (int r = 0; r < 8; r++) { S += R1[r][lx]; Q += R2[r][lx]; }
        float mu = S * (1.0f / DM);
        float var = Q * (1.0f / DM) - mu * mu;
        R1[0][lx] = mu;
        R2[0][lx] = rsqrtf(var + 1e-5f);
    }
    __syncthreads();
    float mu = R1[0][lx], rs = R2[0][lx];
    #pragma unroll
    for (int r = 0; r < 64; r++) {
        int d = ty + r * 8;
        g_h[hbase + (size_t)d * LL] = (v[r] - mu) * rs * gam[d] + bet[d];
    }
}

// ================= mean over L =================
__global__ void mean_kernel()
{
    int row = blockIdx.x;
    size_t base = (size_t)row * LL;
    float s = 0.f;
    for (int l = threadIdx.x; l < LL; l += 128) s += g_h[base + l];
    #pragma unroll
    for (int o = 16; o; o >>= 1) s += __shfl_xor_sync(0xffffffffu, s, o);
    __shared__ float sm[4];
    int wid = threadIdx.x >> 5;
    if ((threadIdx.x & 31) == 0) sm[wid] = s;
    __syncthreads();
    if (threadIdx.x == 0)
        g_hm[row] = (sm[0] + sm[1] + sm[2] + sm[3]) * (1.0f / LL);
}

// ================= stats head =================
__global__ void stats_kernel(const float* __restrict__ Ws,
                             const float* __restrict__ bs,
                             float* __restrict__ out)
{
    int w = (blockIdx.x * blockDim.x + threadIdx.x) >> 5;
    int lane = threadIdx.x & 31;
    int b = w >> 9;
    int o = w & 511;
    const float* hm = g_hm + b * DM;
    const float* wrow = Ws + (size_t)o * DM;
    float s = 0.f;
    for (int d = lane; d < DM; d += 32) s = fmaf(wrow[d], hm[d], s);
    #pragma unroll
    for (int off = 16; off; off >>= 1) s += __shfl_xor_sync(0xffffffffu, s, off);
    if (lane == 0) {
        float v = s + bs[o];
        if (o < 256) out[b * 256 + o] = v;
        else         out[2048 + b * 256 + (o - 256)] = v;
    }
}

// ================= launch =================
extern "C" void kernel_launch(void* const* d_in, const int* in_sizes, int n_in,
                              void* d_out, int out_size)
{
    const float* x      = (const float*)d_in[0];
    const float* Wproj  = (const float*)d_in[1];
    const float* bproj  = (const float*)d_in[2];
    const float* pos    = (const float*)d_in[3];
    const float* log_dt = (const float*)d_in[4];
    const float* logAre = (const float*)d_in[5];
    const float* Aim    = (const float*)d_in[6];
    const float* Cre    = (const float*)d_in[7];
    const float* Cim    = (const float*)d_in[8];
    const float* Dsk    = (const float*)d_in[9];
    const float* Wout   = (const float*)d_in[10];
    const float* bout   = (const float*)d_in[11];
    const float* lng    = (const float*)d_in[12];
    const float* lnb    = (const float*)d_in[13];
    const float* Wstats = (const float*)d_in[14];
    const float* bstats = (const float*)d_in[15];
    float* out = (float*)d_out;

    wsplit_kernel<<<4 * 2 * DM * DM / 256, 256>>>(Wout);
    proj_kernel<<<dim3(LL / 32, DM / 32, BB), dim3(32, 8)>>>(x, Wproj, bproj, pos);

    for (int layer = 0; layer < 4; ++layer) {
        ssm_kernel<<<512, 128>>>(log_dt + layer * DM,
                                 logAre + (size_t)layer * DM * N2C,
                                 Aim    + (size_t)layer * DM * N2C,
                                 Cre    + (size_t)layer * DM * N2C,
                                 Cim    + (size_t)layer * DM * N2C,
                                 Dsk    + layer * DM);
        gemm_mma_kernel<<<dim3(2 * DM / 128, LL / 128, BB), 256>>>(
            layer, bout + layer * 2 * DM);
        glu_ln_kernel<<<dim3(LL / 32, BB), dim3(32, 8)>>>(lng + layer * DM,
                                                          lnb + layer * DM);
    }

    mean_kernel<<<BB * DM, 128>>>();
    stats_kernel<<<512, 256>>>(Wstats, bstats, out);
}

// round 16
// speedup vs baseline: 1.4015x; 1.0057x over previous
#include <cuda_runtime.h>
#include <cuda_bf16.h>
#include <math.h>
#include <stdint.h>

#define BB 8
#define DM 512
#define LL 4096
#define N2C 32
#define NSEG 8
#define SEGL (LL / NSEG)          // 512
#define SEGCH (SEGL / 16)         // 32 chunks per segment

typedef unsigned long long u64;
typedef unsigned int u32;

union F2 { u64 u; float2 f; };

__device__ __forceinline__ u64 fma2(u64 a, u64 b, u64 c) {
    u64 d; asm("fma.rn.f32x2 %0, %1, %2, %3;" : "=l"(d) : "l"(a), "l"(b), "l"(c)); return d;
}
__device__ __forceinline__ u64 mul2(u64 a, u64 b) {
    u64 d; asm("mul.rn.f32x2 %0, %1, %2;" : "=l"(d) : "l"(a), "l"(b)); return d;
}
__device__ __forceinline__ u64 pack2(float lo, float hi) {
    u64 d; asm("mov.b64 %0, {%1, %2};" : "=l"(d) : "f"(lo), "f"(hi)); return d;
}

// ---------------- scratch (__device__ globals; no allocs allowed) ----------------
__device__ float g_h[(size_t)BB * DM * LL];                // residual (B,D,L)
__device__ __nv_bfloat16 g_yhi[(size_t)BB * DM * LL];      // S4D+gelu output, bf16 hi
__device__ __nv_bfloat16 g_ylo[(size_t)BB * DM * LL];      // S4D+gelu output, bf16 lo
__device__ float g_p[(size_t)BB * 2 * DM * LL];            // GEMM preactivations
__device__ __nv_bfloat16 g_whi[(size_t)4 * 2 * DM * DM];   // W split hi
__device__ __nv_bfloat16 g_wlo[(size_t)4 * 2 * DM * DM];   // W split lo
__device__ float g_hm[BB * DM];
__device__ float2 g_cend[NSEG - 1][BB * DM][N2C];          // pass1 local end states
__device__ float2 g_sinit[NSEG - 1][BB * DM][N2C];         // init states for segs 1..7

// ================= warp-MMA primitives (baseline ISA, OK on plain sm_103) ===
__device__ __forceinline__ u32 smem_u32(const void* p) {
    u32 a;
    asm("{ .reg .u64 t; cvta.to.shared.u64 t, %1; cvt.u32.u64 %0, t; }" : "=r"(a) : "l"(p));
    return a;
}
__device__ __forceinline__ void mma16816(float* d, const u32* a, const u32* b) {
    asm volatile("mma.sync.aligned.m16n8k16.row.col.f32.bf16.bf16.f32 "
        "{%0,%1,%2,%3}, {%4,%5,%6,%7}, {%8,%9}, {%0,%1,%2,%3};"
        : "+f"(d[0]), "+f"(d[1]), "+f"(d[2]), "+f"(d[3])
        : "r"(a[0]), "r"(a[1]), "r"(a[2]), "r"(a[3]), "r"(b[0]), "r"(b[1]));
}
__device__ __forceinline__ void ldsm4(u32* r, u32 addr) {
    asm volatile("ldmatrix.sync.aligned.m8n8.x4.shared.b16 {%0,%1,%2,%3}, [%4];"
        : "=r"(r[0]), "=r"(r[1]), "=r"(r[2]), "=r"(r[3]) : "r"(addr));
}
__device__ __forceinline__ void ldsm4t(u32* r, u32 addr) {
    asm volatile("ldmatrix.sync.aligned.m8n8.x4.trans.shared.b16 {%0,%1,%2,%3}, [%4];"
        : "=r"(r[0]), "=r"(r[1]), "=r"(r[2]), "=r"(r[3]) : "r"(addr));
}

// ================= W split (all 4 layers, once per launch) =================
__global__ void wsplit_kernel(const float* __restrict__ W)
{
    int i = blockIdx.x * 256 + threadIdx.x;
    float w = W[i];
    __nv_bfloat16 h = __float2bfloat16_rn(w);
    g_whi[i] = h;
    g_wlo[i] = __float2bfloat16_rn(w - __bfloat162float(h));
}

// ================= input projection + positional embedding =================
__global__ void proj_kernel(const float* __restrict__ x,
                            const float* __restrict__ Wp,
                            const float* __restrict__ bp,
                            const float* __restrict__ pos)
{
    __shared__ float P[32][33];
    int lx = threadIdx.x, ty = threadIdx.y;
    int l0 = blockIdx.x * 32, d0 = blockIdx.y * 32, b = blockIdx.z;
    #pragma unroll
    for (int r = 0; r < 4; r++) {
        int ll = ty + r * 8;
        P[ll][lx] = pos[(size_t)(l0 + ll) * DM + d0 + lx];
    }
    __syncthreads();
    int l = l0 + lx;
    float x0 = x[(size_t)(b * 3 + 0) * LL + l];
    float x1 = x[(size_t)(b * 3 + 1) * LL + l];
    float x2 = x[(size_t)(b * 3 + 2) * LL + l];
    #pragma unroll
    for (int r = 0; r < 4; r++) {
        int dl = ty * 4 + r;
        int d = d0 + dl;
        float v = Wp[d * 3 + 0] * x0 + Wp[d * 3 + 1] * x1 + Wp[d * 3 + 2] * x2
                + bp[d] + P[lx][dl];
        g_h[(size_t)(b * DM + d) * LL + l] = v;
    }
}

// ---------------- shared S4D param setup ----------------
struct SsmP { u64 wr2, wi2, nwi2, Ccr2, nCci2; float dt, Dsk; };

__device__ __forceinline__ SsmP ssm_params(
    int hch, int sub,
    const float* log_dt, const float* log_A_real, const float* A_imag,
    const float* C_re, const float* C_im, const float* Dskip, bool want_c)
{
    SsmP P;
    P.dt  = expf(log_dt[hch]);
    P.Dsk = want_c ? Dskip[hch] : 0.f;
    float wrv[2], wiv[2], Ccrv[2], nCciv[2];
    #pragma unroll
    for (int j = 0; j < 2; j++) {
        int n   = sub + 16 * j;
        int idx = hch * N2C + n;
        float Are = -expf(log_A_real[idx]);
        float Aim = A_imag[idx];
        float dr = Are * P.dt, di = Aim * P.dt;
        float er = expf(dr);
        float wrr = er * cosf(di), wii = er * sinf(di);
        wrv[j] = wrr; wiv[j] = wii;
        if (want_c) {
            float nr = wrr - 1.0f, ni = wii;
            float inv = 1.0f / (Are * Are + Aim * Aim);
            float qr = (nr * Are + ni * Aim) * inv;
            float qi = (ni * Are - nr * Aim) * inv;
            float cr = C_re[idx], ci = C_im[idx];
            Ccrv[j]  =  2.0f * (cr * qr - ci * qi);
            nCciv[j] = -2.0f * (cr * qi + ci * qr);
        } else { Ccrv[j] = 0.f; nCciv[j] = 0.f; }
    }
    P.wr2   = pack2(wrv[0],  wrv[1]);
    P.wi2   = pack2(wiv[0],  wiv[1]);
    P.nwi2  = pack2(-wiv[0], -wiv[1]);
    P.Ccr2  = pack2(Ccrv[0], Ccrv[1]);
    P.nCci2 = pack2(nCciv[0], nCciv[1]);
    return P;
}

// ================= SSM pass 1: local end-states of segments 0..6 ============
__global__ __launch_bounds__(128) void ssm_pass1(
    const float* __restrict__ log_dt,
    const float* __restrict__ log_A_real,
    const float* __restrict__ A_imag)
{
    int seg  = blockIdx.y;                     // 0..6
    int w    = blockIdx.x * 4 + (threadIdx.x >> 5);
    int lane = threadIdx.x & 31;
    int g = lane >> 4, sub = lane & 15;
    int b = w >> 8;
    int hch = (w & 255) * 2 + g;
    int row = b * DM + hch;

    SsmP P = ssm_params(hch, sub, log_dt, log_A_real, A_imag, 0, 0, 0, false);

    const float* up = g_h + (size_t)row * LL + seg * SEGL;
    u64 sr2 = 0ull, si2 = 0ull;
    float4 uv[4], nv[4];
    #pragma unroll
    for (int q = 0; q < 4; q++) uv[q] = *(const float4*)(up + q * 4);

    for (int c = 0; c < SEGCH; c++) {
        if (c + 1 < SEGCH) {
            #pragma unroll
            for (int q = 0; q < 4; q++)
                nv[q] = *(const float4*)(up + (c + 1) * 16 + q * 4);
        }
        #pragma unroll
        for (int t = 0; t < 16; t++) {
            float4 vq = uv[t >> 2];
            int cc = t & 3;
            float ut = (cc == 0) ? vq.x : (cc == 1) ? vq.y : (cc == 2) ? vq.z : vq.w;
            u64 ut2 = pack2(ut, ut);
            u64 a2  = fma2(P.nwi2, si2, ut2);
            u64 b2  = fma2(P.wr2, si2, mul2(P.wi2, sr2));
            sr2 = fma2(P.wr2, sr2, a2);
            si2 = b2;
        }
        #pragma unroll
        for (int q = 0; q < 4; q++) uv[q] = nv[q];
    }
    F2 fr, fi; fr.u = sr2; fi.u = si2;
    g_cend[seg][row][sub]      = make_float2(fr.f.x, fi.f.x);
    g_cend[seg][row][sub + 16] = make_float2(fr.f.y, fi.f.y);
}

// ================= SSM combine: propagate boundary states ===================
// S_{j+1} = W * S_j + c_j,  W = exp(SEGL * dt * A) computed directly.
__global__ void ssm_combine(
    const float* __restrict__ log_dt,
    const float* __restrict__ log_A_real,
    const float* __restrict__ A_imag)
{
    int t = blockIdx.x * 256 + threadIdx.x;    // 131072 states
    int b = t >> 14;
    int rem = t & 16383;
    int ch = rem >> 5;
    int n  = rem & 31;
    int row = b * DM + ch;
    int idx = ch * N2C + n;

    float dt  = expf(log_dt[ch]);
    float Are = -expf(log_A_real[idx]);
    float Aim = A_imag[idx];
    float mag = expf((float)SEGL * Are * dt);
    double ang = (double)SEGL * (double)Aim * (double)dt;
    float Wre = mag * (float)cos(ang);
    float Wim = mag * (float)sin(ang);

    float Sr = 0.f, Si = 0.f;
    #pragma unroll
    for (int j = 0; j < NSEG - 1; j++) {
        float2 c = g_cend[j][row][n];
        float nr = Wre * Sr - Wim * Si + c.x;
        float ni = Wre * Si + Wim * Sr + c.y;
        Sr = nr; Si = ni;
        g_sinit[j][row][n] = make_float2(Sr, Si);
    }
}

// ================= SSM pass 2: outputs with correct inits ===================
__global__ __launch_bounds__(128) void ssm_pass2(
    const float* __restrict__ log_dt,
    const float* __restrict__ log_A_real,
    const float* __restrict__ A_imag,
    const float* __restrict__ C_re,
    const float* __restrict__ C_im,
    const float* __restrict__ Dskip)
{
    int seg  = blockIdx.y;                     // 0..7
    int w    = blockIdx.x * 4 + (threadIdx.x >> 5);
    int lane = threadIdx.x & 31;
    int g = lane >> 4, sub = lane & 15;
    int b = w >> 8;
    int hch = (w & 255) * 2 + g;
    int row = b * DM + hch;

    SsmP P = ssm_params(hch, sub, log_dt, log_A_real, A_imag, C_re, C_im, Dskip, true);

    size_t off = (size_t)row * LL + seg * SEGL;
    const float* up = g_h + off;
    __nv_bfloat16* yhp = g_yhi + off;
    __nv_bfloat16* ylp = g_ylo + off;

    u64 sr2 = 0ull, si2 = 0ull;
    if (seg > 0) {
        float2 s0 = g_sinit[seg - 1][row][sub];
        float2 s1 = g_sinit[seg - 1][row][sub + 16];
        sr2 = pack2(s0.x, s1.x);
        si2 = pack2(s0.y, s1.y);
    }

    float4 uv[4], nv[4];
    #pragma unroll
    for (int q = 0; q < 4; q++) uv[q] = *(const float4*)(up + q * 4);

    for (int c = 0; c < SEGCH; c++) {
        if (c + 1 < SEGCH) {
            #pragma unroll
            for (int q = 0; q < 4; q++)
                nv[q] = *(const float4*)(up + (c + 1) * 16 + q * 4);
        }
        u64 y2[16];
        #pragma unroll
        for (int t = 0; t < 16; t++) y2[t] = 0ull;
        float uown = 0.f;
        #pragma unroll
        for (int t = 0; t < 16; t++) {
            float4 vq = uv[t >> 2];
            int cc = t & 3;
            float ut = (cc == 0) ? vq.x : (cc == 1) ? vq.y : (cc == 2) ? vq.z : vq.w;
            u64 ut2 = pack2(ut, ut);
            u64 a2  = fma2(P.nwi2, si2, ut2);
            u64 b2  = fma2(P.wr2, si2, mul2(P.wi2, sr2));
            sr2 = fma2(P.wr2, sr2, a2);
            si2 = b2;
            y2[t] = fma2(P.Ccr2, sr2, y2[t]);
            y2[t] = fma2(P.nCci2, si2, y2[t]);
            if (sub == t) uown = ut;
        }
        float a[16];
        #pragma unroll
        for (int t = 0; t < 16; t++) { F2 f; f.u = y2[t]; a[t] = f.f.x + f.f.y; }
        #pragma unroll
        for (int m = 8, cnt = 16; m >= 1; m >>= 1, cnt >>= 1) {
            bool hi = (sub & m) != 0;
            #pragma unroll
            for (int i = 0; i < 8; i++) {
                if (i < cnt / 2) {
                    float send = hi ? a[i] : a[i + cnt / 2];
                    float keep = hi ? a[i + cnt / 2] : a[i];
                    a[i] = keep + __shfl_xor_sync(0xffffffffu, send, m);
                }
            }
        }
        float v   = fmaf(P.Dsk, uown, a[0]);
        float gel = 0.5f * v * (1.0f + erff(v * 0.70710678118654752f));
        __nv_bfloat16 h = __float2bfloat16_rn(gel);
        yhp[c * 16 + sub] = h;
        ylp[c * 16 + sub] = __float2bfloat16_rn(gel - __bfloat162float(h));
        #pragma unroll
        for (int q = 0; q < 4; q++) uv[q] = nv[q];
    }
}

// ================= bf16-split warp-MMA GEMM (double-buffered smem) ==========
#define BKC 32
#define KSTEPS (DM / BKC)    // 16
#define ASTR 144
#define BSTR 272
#define SMA  0
#define SMBH (128 * ASTR)            // 18432
#define SMBL (SMBH + 32 * BSTR)      // 27136
#define SMTOT (SMBL + 32 * BSTR)     // 35840

__global__ __launch_bounds__(256) void gemm_mma_kernel(
    int layer,
    const float* __restrict__ bias)
{
    extern __shared__ __align__(16) char sm[];

    int tid = threadIdx.x;
    int lane = tid & 31, warp = tid >> 5;
    int grp = lane >> 2, tig = lane & 3;
    int wm = warp & 1, wn = warp >> 1;
    int m0 = blockIdx.x * 128;
    int n0 = blockIdx.y * 128;
    int bz = blockIdx.z;

    const __nv_bfloat16* whi_t = g_whi + (size_t)layer * 2 * DM * DM + (size_t)m0 * DM;
    const __nv_bfloat16* wlo_t = g_wlo + (size_t)layer * 2 * DM * DM + (size_t)m0 * DM;
    const __nv_bfloat16* yhi_b = g_yhi + (size_t)bz * DM * LL + n0;
    const __nv_bfloat16* ylo_b = g_ylo + (size_t)bz * DM * LL + n0;

    u32 smu = smem_u32(sm);

    float acc[4][4][4];
    #pragma unroll
    for (int i = 0; i < 4; i++)
        #pragma unroll
        for (int j = 0; j < 4; j++)
            #pragma unroll
            for (int q = 0; q < 4; q++) acc[i][j][q] = 0.f;

    int arow = tid >> 3;
    int aseg = tid & 7;
    int asplit = aseg >> 2;
    int akoff = (aseg & 3) * 8;
    const __nv_bfloat16* wsrc = asplit ? wlo_t : whi_t;
    int brow = tid >> 4;
    int bseg = tid & 15;

    uint4 rA[4], rBh[2], rBl[2];

#define GLOAD(k0) do {                                                          \
        _Pragma("unroll") for (int i = 0; i < 4; i++)                           \
            rA[i] = *(const uint4*)(wsrc + (size_t)(arow + 32 * i) * DM + (k0) + akoff); \
        _Pragma("unroll") for (int i = 0; i < 2; i++) {                         \
            size_t off = (size_t)((k0) + brow + 16 * i) * LL + bseg * 8;        \
            rBh[i] = *(const uint4*)(yhi_b + off);                              \
            rBl[i] = *(const uint4*)(ylo_b + off);                              \
        }                                                                       \
    } while (0)

#define SSTORE(base) do {                                                       \
        _Pragma("unroll") for (int i = 0; i < 4; i++)                           \
            *(uint4*)(sm + (base) + SMA + (arow + 32 * i) * ASTR + asplit * 64 + (aseg & 3) * 16) = rA[i]; \
        _Pragma("unroll") for (int i = 0; i < 2; i++) {                         \
            *(uint4*)(sm + (base) + SMBH + (brow + 16 * i) * BSTR + bseg * 16) = rBh[i]; \
            *(uint4*)(sm + (base) + SMBL + (brow + 16 * i) * BSTR + bseg * 16) = rBl[i]; \
        }                                                                       \
    } while (0)

    GLOAD(0);
    SSTORE(0);
    __syncthreads();

    int a_r = lane & 15;
    int a_c = (lane >> 4) << 4;
    int b_r = (lane & 7) + ((lane >> 3) & 1) * 8;
    int b_c = (lane >> 4) << 4;

    for (int c = 0; c < KSTEPS; c++) {
        u32 cur = (u32)(c & 1) * SMTOT;
        if (c + 1 < KSTEPS) GLOAD((c + 1) * BKC);
        #pragma unroll
        for (int kk = 0; kk < 2; kk++) {
            u32 bfh[4][2], bfl[4][2];
            #pragma unroll
            for (int t = 0; t < 2; t++) {
                u32 rr[4];
                u32 browl = (u32)(kk * 16 + b_r);
                u32 bcol  = (u32)((wn * 32 + t * 16) * 2 + b_c);
                ldsm4t(rr, smu + cur + SMBH + browl * BSTR + bcol);
                bfh[2 * t][0] = rr[0]; bfh[2 * t][1] = rr[1];
                bfh[2 * t + 1][0] = rr[2]; bfh[2 * t + 1][1] = rr[3];
                ldsm4t(rr, smu + cur + SMBL + browl * BSTR + bcol);
                bfl[2 * t][0] = rr[0]; bfl[2 * t][1] = rr[1];
                bfl[2 * t + 1][0] = rr[2]; bfl[2 * t + 1][1] = rr[3];
            }
            #pragma unroll
            for (int mt = 0; mt < 4; mt++) {
                u32 af[4], al[4];
                u32 arowl = (u32)(wm * 64 + mt * 16 + a_r);
                u32 acol  = (u32)(kk * 32 + a_c);
                ldsm4(af, smu + cur + SMA + arowl * ASTR + acol);
                ldsm4(al, smu + cur + SMA + arowl * ASTR + 64 + acol);
                #pragma unroll
                for (int nt = 0; nt < 4; nt++) {
                    mma16816(acc[mt][nt], af, bfh[nt]);   // hi*hi
                    mma16816(acc[mt][nt], al, bfh[nt]);   // lo*hi
                    mma16816(acc[mt][nt], af, bfl[nt]);   // hi*lo
                }
            }
        }
        if (c + 1 < KSTEPS) {
            SSTORE((u32)((c + 1) & 1) * SMTOT);
            __syncthreads();
        }
    }

    float* Pp = g_p + (size_t)bz * 2 * DM * LL;
    #pragma unroll
    for (int mt = 0; mt < 4; mt++) {
        int r0 = m0 + wm * 64 + mt * 16 + grp;
        float bv0 = bias[r0];
        float bv1 = bias[r0 + 8];
        #pragma unroll
        for (int nt = 0; nt < 4; nt++) {
            int col = n0 + wn * 32 + nt * 8 + tig * 2;
            float2 v0 = {acc[mt][nt][0] + bv0, acc[mt][nt][1] + bv0};
            float2 v1 = {acc[mt][nt][2] + bv1, acc[mt][nt][3] + bv1};
            *(float2*)(Pp + (size_t)r0 * LL + col) = v0;
            *(float2*)(Pp + (size_t)(r0 + 8) * LL + col) = v1;
        }
    }
}

// ================= fused GLU + residual + LayerNorm =================
__global__ __launch_bounds__(256) void glu_ln_kernel(const float* __restrict__ gam,
                                                     const float* __restrict__ bet)
{
    int lx = threadIdx.x, ty = threadIdx.y;
    int l = blockIdx.x * 32 + lx;
    int b = blockIdx.y;
    __shared__ float R1[8][32], R2[8][32];
    size_t hbase = (size_t)b * DM * LL + l;
    size_t pbase = (size_t)b * 2 * DM * LL + l;
    float v[64];
    float s = 0.f, q = 0.f;
    #pragma unroll
    for (int r = 0; r < 64; r++) {
        int d = ty + r * 8;
        float a    = g_p[pbase + (size_t)d * LL];
        float gate = g_p[pbase + (size_t)(d + DM) * LL];
        float vv = g_h[hbase + (size_t)d * LL] + a / (1.0f + expf(-gate));
        v[r] = vv;
        s += vv; q = fmaf(vv, vv, q);
    }
    R1[ty][lx] = s; R2[ty][lx] = q;
    __syncthreads();
    if (ty == 0) {
        float S = 0.f, Q = 0.f;
        #pragma unroll
        for (int r = 0; r < 8; r++) { S += R1[r][lx]; Q += R2[r][lx]; }
        float mu = S * (1.0f / DM);
        float var = Q * (1.0f / DM) - mu * mu;
        R1[0][lx] = mu;
        R2[0][lx] = rsqrtf(var + 1e-5f);
    }
    __syncthreads();
    float mu = R1[0][lx], rs = R2[0][lx];
    #pragma unroll
    for (int r = 0; r < 64; r++) {
        int d = ty + r * 8;
        g_h[hbase + (size_t)d * LL] = (v[r] - mu) * rs * gam[d] + bet[d];
    }
}

// ================= mean over L =================
__global__ void mean_kernel()
{
    int row = blockIdx.x;
    size_t base = (size_t)row * LL;
    float s = 0.f;
    for (int l = threadIdx.x; l < LL; l += 128) s += g_h[base + l];
    #pragma unroll
    for (int o = 16; o; o >>= 1) s += __shfl_xor_sync(0xffffffffu, s, o);
    __shared__ float sm[4];
    int wid = threadIdx.x >> 5;
    if ((threadIdx.x & 31) == 0) sm[wid] = s;
    __syncthreads();
    if (threadIdx.x == 0)
        g_hm[row] = (sm[0] + sm[1] + sm[2] + sm[3]) * (1.0f / LL);
}

// ================= stats head =================
__global__ void stats_kernel(const float* __restrict__ Ws,
                             const float* __restrict__ bs,
                             float* __restrict__ out)
{
    int w = (blockIdx.x * blockDim.x + threadIdx.x) >> 5;
    int lane = threadIdx.x & 31;
    int b = w >> 9;
    int o = w & 511;
    const float* hm = g_hm + b * DM;
    const float* wrow = Ws + (size_t)o * DM;
    float s = 0.f;
    for (int d = lane; d < DM; d += 32) s = fmaf(wrow[d], hm[d], s);
    #pragma unroll
    for (int off = 16; off; off >>= 1) s += __shfl_xor_sync(0xffffffffu, s, off);
    if (lane == 0) {
        float v = s + bs[o];
        if (o < 256) out[b * 256 + o] = v;
        else         out[2048 + b * 256 + (o - 256)] = v;
    }
}

// ================= launch =================
extern "C" void kernel_launch(void* const* d_in, const int* in_sizes, int n_in,
                              void* d_out, int out_size)
{
    const float* x      = (const float*)d_in[0];
    const float* Wproj  = (const float*)d_in[1];
    const float* bproj  = (const float*)d_in[2];
    const float* pos    = (const float*)d_in[3];
    const float* log_dt = (const float*)d_in[4];
    const float* logAre = (const float*)d_in[5];
    const float* Aim    = (const float*)d_in[6];
    const float* Cre    = (const float*)d_in[7];
    const float* Cim    = (const float*)d_in[8];
    const float* Dsk    = (const float*)d_in[9];
    const float* Wout   = (const float*)d_in[10];
    const float* bout   = (const float*)d_in[11];
    const float* lng    = (const float*)d_in[12];
    const float* lnb    = (const float*)d_in[13];
    const float* Wstats = (const float*)d_in[14];
    const float* bstats = (const float*)d_in[15];
    float* out = (float*)d_out;

    cudaFuncSetAttribute(gemm_mma_kernel,
                         cudaFuncAttributeMaxDynamicSharedMemorySize, 2 * SMTOT);

    wsplit_kernel<<<4 * 2 * DM * DM / 256, 256>>>(Wout);
    proj_kernel<<<dim3(LL / 32, DM / 32, BB), dim3(32, 8)>>>(x, Wproj, bproj, pos);

    for (int layer = 0; layer < 4; ++layer) {
        const float* ld = log_dt + layer * DM;
        const float* la = logAre + (size_t)layer * DM * N2C;
        const float* ai = Aim    + (size_t)layer * DM * N2C;
        ssm_pass1<<<dim3(512, NSEG - 1), 128>>>(ld, la, ai);
        ssm_combine<<<BB * DM * N2C / 256, 256>>>(ld, la, ai);
        ssm_pass2<<<dim3(512, NSEG), 128>>>(ld, la, ai,
                                            Cre + (size_t)layer * DM * N2C,
                                            Cim + (size_t)layer * DM * N2C,
                                            Dsk + layer * DM);
        gemm_mma_kernel<<<dim3(2 * DM / 128, LL / 128, BB), 256, 2 * SMTOT>>>(
            layer, bout + layer * 2 * DM);
        glu_ln_kernel<<<dim3(LL / 32, BB), dim3(32, 8)>>>(lng + layer * DM,
                                                          lnb + layer * DM);
    }

    mean_kernel<<<BB * DM, 128>>>();
    stats_kernel<<<512, 256>>>(Wstats, bstats, out);
}

// round 17
// speedup vs baseline: 1.4393x; 1.0270x over previous
#include <cuda_runtime.h>
#include <cuda_bf16.h>
#include <math.h>
#include <stdint.h>

#define BB 8
#define DM 512
#define LL 4096
#define N2C 32
#define NSEG 8
#define SEGL (LL / NSEG)          // 512
#define SEGCH (SEGL / 16)         // 32 chunks per segment

typedef unsigned long long u64;
typedef unsigned int u32;

union F2 { u64 u; float2 f; };

__device__ __forceinline__ u64 fma2(u64 a, u64 b, u64 c) {
    u64 d; asm("fma.rn.f32x2 %0, %1, %2, %3;" : "=l"(d) : "l"(a), "l"(b), "l"(c)); return d;
}
__device__ __forceinline__ u64 mul2(u64 a, u64 b) {
    u64 d; asm("mul.rn.f32x2 %0, %1, %2;" : "=l"(d) : "l"(a), "l"(b)); return d;
}
__device__ __forceinline__ u64 pack2(float lo, float hi) {
    u64 d; asm("mov.b64 %0, {%1, %2};" : "=l"(d) : "f"(lo), "f"(hi)); return d;
}

// ---------------- scratch (__device__ globals; no allocs allowed) ----------------
__device__ float g_h[(size_t)BB * DM * LL];                // residual (B,D,L)
__device__ __nv_bfloat16 g_yhi[(size_t)BB * DM * LL];      // S4D+gelu output, bf16 hi
__device__ __nv_bfloat16 g_ylo[(size_t)BB * DM * LL];      // S4D+gelu output, bf16 lo
__device__ float g_p[(size_t)BB * 2 * DM * LL];            // GLU output z (first half used)
__device__ __nv_bfloat16 g_whi[(size_t)4 * 2 * DM * DM];   // W split hi
__device__ __nv_bfloat16 g_wlo[(size_t)4 * 2 * DM * DM];   // W split lo
__device__ float g_hm[BB * DM];
__device__ float2 g_cend[NSEG - 1][BB * DM][N2C];          // pass1 local end states
__device__ float2 g_sinit[NSEG - 1][BB * DM][N2C];         // init states for segs 1..7

// ================= warp-MMA primitives (baseline ISA, OK on plain sm_103) ===
__device__ __forceinline__ u32 smem_u32(const void* p) {
    u32 a;
    asm("{ .reg .u64 t; cvta.to.shared.u64 t, %1; cvt.u32.u64 %0, t; }" : "=r"(a) : "l"(p));
    return a;
}
__device__ __forceinline__ void mma16816(float* d, const u32* a, const u32* b) {
    asm volatile("mma.sync.aligned.m16n8k16.row.col.f32.bf16.bf16.f32 "
        "{%0,%1,%2,%3}, {%4,%5,%6,%7}, {%8,%9}, {%0,%1,%2,%3};"
        : "+f"(d[0]), "+f"(d[1]), "+f"(d[2]), "+f"(d[3])
        : "r"(a[0]), "r"(a[1]), "r"(a[2]), "r"(a[3]), "r"(b[0]), "r"(b[1]));
}
__device__ __forceinline__ void ldsm4(u32* r, u32 addr) {
    asm volatile("ldmatrix.sync.aligned.m8n8.x4.shared.b16 {%0,%1,%2,%3}, [%4];"
        : "=r"(r[0]), "=r"(r[1]), "=r"(r[2]), "=r"(r[3]) : "r"(addr));
}
__device__ __forceinline__ void ldsm4t(u32* r, u32 addr) {
    asm volatile("ldmatrix.sync.aligned.m8n8.x4.trans.shared.b16 {%0,%1,%2,%3}, [%4];"
        : "=r"(r[0]), "=r"(r[1]), "=r"(r[2]), "=r"(r[3]) : "r"(addr));
}

// ================= W split (all 4 layers, once per launch) =================
__global__ void wsplit_kernel(const float* __restrict__ W)
{
    int i = blockIdx.x * 256 + threadIdx.x;
    float w = W[i];
    __nv_bfloat16 h = __float2bfloat16_rn(w);
    g_whi[i] = h;
    g_wlo[i] = __float2bfloat16_rn(w - __bfloat162float(h));
}

// ================= input projection + positional embedding =================
__global__ void proj_kernel(const float* __restrict__ x,
                            const float* __restrict__ Wp,
                            const float* __restrict__ bp,
                            const float* __restrict__ pos)
{
    __shared__ float P[32][33];
    int lx = threadIdx.x, ty = threadIdx.y;
    int l0 = blockIdx.x * 32, d0 = blockIdx.y * 32, b = blockIdx.z;
    #pragma unroll
    for (int r = 0; r < 4; r++) {
        int ll = ty + r * 8;
        P[ll][lx] = pos[(size_t)(l0 + ll) * DM + d0 + lx];
    }
    __syncthreads();
    int l = l0 + lx;
    float x0 = x[(size_t)(b * 3 + 0) * LL + l];
    float x1 = x[(size_t)(b * 3 + 1) * LL + l];
    float x2 = x[(size_t)(b * 3 + 2) * LL + l];
    #pragma unroll
    for (int r = 0; r < 4; r++) {
        int dl = ty * 4 + r;
        int d = d0 + dl;
        float v = Wp[d * 3 + 0] * x0 + Wp[d * 3 + 1] * x1 + Wp[d * 3 + 2] * x2
                + bp[d] + P[lx][dl];
        g_h[(size_t)(b * DM + d) * LL + l] = v;
    }
}

// ---------------- shared S4D param setup ----------------
struct SsmP { u64 wr2, wi2, nwi2, Ccr2, nCci2; float dt, Dsk; };

__device__ __forceinline__ SsmP ssm_params(
    int hch, int sub,
    const float* log_dt, const float* log_A_real, const float* A_imag,
    const float* C_re, const float* C_im, const float* Dskip, bool want_c)
{
    SsmP P;
    P.dt  = expf(log_dt[hch]);
    P.Dsk = want_c ? Dskip[hch] : 0.f;
    float wrv[2], wiv[2], Ccrv[2], nCciv[2];
    #pragma unroll
    for (int j = 0; j < 2; j++) {
        int n   = sub + 16 * j;
        int idx = hch * N2C + n;
        float Are = -expf(log_A_real[idx]);
        float Aim = A_imag[idx];
        float dr = Are * P.dt, di = Aim * P.dt;
        float er = expf(dr);
        float wrr = er * cosf(di), wii = er * sinf(di);
        wrv[j] = wrr; wiv[j] = wii;
        if (want_c) {
            float nr = wrr - 1.0f, ni = wii;
            float inv = 1.0f / (Are * Are + Aim * Aim);
            float qr = (nr * Are + ni * Aim) * inv;
            float qi = (ni * Are - nr * Aim) * inv;
            float cr = C_re[idx], ci = C_im[idx];
            Ccrv[j]  =  2.0f * (cr * qr - ci * qi);
            nCciv[j] = -2.0f * (cr * qi + ci * qr);
        } else { Ccrv[j] = 0.f; nCciv[j] = 0.f; }
    }
    P.wr2   = pack2(wrv[0],  wrv[1]);
    P.wi2   = pack2(wiv[0],  wiv[1]);
    P.nwi2  = pack2(-wiv[0], -wiv[1]);
    P.Ccr2  = pack2(Ccrv[0], Ccrv[1]);
    P.nCci2 = pack2(nCciv[0], nCciv[1]);
    return P;
}

// ================= SSM pass 1: local end-states of segments 0..6 ============
__global__ __launch_bounds__(128) void ssm_pass1(
    const float* __restrict__ log_dt,
    const float* __restrict__ log_A_real,
    const float* __restrict__ A_imag)
{
    int seg  = blockIdx.y;
    int w    = blockIdx.x * 4 + (threadIdx.x >> 5);
    int lane = threadIdx.x & 31;
    int g = lane >> 4, sub = lane & 15;
    int b = w >> 8;
    int hch = (w & 255) * 2 + g;
    int row = b * DM + hch;

    SsmP P = ssm_params(hch, sub, log_dt, log_A_real, A_imag, 0, 0, 0, false);

    const float* up = g_h + (size_t)row * LL + seg * SEGL;
    u64 sr2 = 0ull, si2 = 0ull;
    float4 uv[4], nv[4];
    #pragma unroll
    for (int q = 0; q < 4; q++) uv[q] = *(const float4*)(up + q * 4);

    for (int c = 0; c < SEGCH; c++) {
        if (c + 1 < SEGCH) {
            #pragma unroll
            for (int q = 0; q < 4; q++)
                nv[q] = *(const float4*)(up + (c + 1) * 16 + q * 4);
        }
        #pragma unroll
        for (int t = 0; t < 16; t++) {
            float4 vq = uv[t >> 2];
            int cc = t & 3;
            float ut = (cc == 0) ? vq.x : (cc == 1) ? vq.y : (cc == 2) ? vq.z : vq.w;
            u64 ut2 = pack2(ut, ut);
            u64 a2  = fma2(P.nwi2, si2, ut2);
            u64 b2  = fma2(P.wr2, si2, mul2(P.wi2, sr2));
            sr2 = fma2(P.wr2, sr2, a2);
            si2 = b2;
        }
        #pragma unroll
        for (int q = 0; q < 4; q++) uv[q] = nv[q];
    }
    F2 fr, fi; fr.u = sr2; fi.u = si2;
    g_cend[seg][row][sub]      = make_float2(fr.f.x, fi.f.x);
    g_cend[seg][row][sub + 16] = make_float2(fr.f.y, fi.f.y);
}

// ================= SSM combine: propagate boundary states ===================
__global__ void ssm_combine(
    const float* __restrict__ log_dt,
    const float* __restrict__ log_A_real,
    const float* __restrict__ A_imag)
{
    int t = blockIdx.x * 256 + threadIdx.x;
    int b = t >> 14;
    int rem = t & 16383;
    int ch = rem >> 5;
    int n  = rem & 31;
    int row = b * DM + ch;
    int idx = ch * N2C + n;

    float dt  = expf(log_dt[ch]);
    float Are = -expf(log_A_real[idx]);
    float Aim = A_imag[idx];
    float mag = expf((float)SEGL * Are * dt);
    double ang = (double)SEGL * (double)Aim * (double)dt;
    float Wre = mag * (float)cos(ang);
    float Wim = mag * (float)sin(ang);

    float Sr = 0.f, Si = 0.f;
    #pragma unroll
    for (int j = 0; j < NSEG - 1; j++) {
        float2 c = g_cend[j][row][n];
        float nr = Wre * Sr - Wim * Si + c.x;
        float ni = Wre * Si + Wim * Sr + c.y;
        Sr = nr; Si = ni;
        g_sinit[j][row][n] = make_float2(Sr, Si);
    }
}

// ================= SSM pass 2: outputs with correct inits ===================
__global__ __launch_bounds__(128) void ssm_pass2(
    const float* __restrict__ log_dt,
    const float* __restrict__ log_A_real,
    const float* __restrict__ A_imag,
    const float* __restrict__ C_re,
    const float* __restrict__ C_im,
    const float* __restrict__ Dskip)
{
    int seg  = blockIdx.y;
    int w    = blockIdx.x * 4 + (threadIdx.x >> 5);
    int lane = threadIdx.x & 31;
    int g = lane >> 4, sub = lane & 15;
    int b = w >> 8;
    int hch = (w & 255) * 2 + g;
    int row = b * DM + hch;

    SsmP P = ssm_params(hch, sub, log_dt, log_A_real, A_imag, C_re, C_im, Dskip, true);

    size_t off = (size_t)row * LL + seg * SEGL;
    const float* up = g_h + off;
    __nv_bfloat16* yhp = g_yhi + off;
    __nv_bfloat16* ylp = g_ylo + off;

    u64 sr2 = 0ull, si2 = 0ull;
    if (seg > 0) {
        float2 s0 = g_sinit[seg - 1][row][sub];
        float2 s1 = g_sinit[seg - 1][row][sub + 16];
        sr2 = pack2(s0.x, s1.x);
        si2 = pack2(s0.y, s1.y);
    }

    float4 uv[4], nv[4];
    #pragma unroll
    for (int q = 0; q < 4; q++) uv[q] = *(const float4*)(up + q * 4);

    for (int c = 0; c < SEGCH; c++) {
        if (c + 1 < SEGCH) {
            #pragma unroll
            for (int q = 0; q < 4; q++)
                nv[q] = *(const float4*)(up + (c + 1) * 16 + q * 4);
        }
        u64 y2[16];
        #pragma unroll
        for (int t = 0; t < 16; t++) y2[t] = 0ull;
        float uown = 0.f;
        #pragma unroll
        for (int t = 0; t < 16; t++) {
            float4 vq = uv[t >> 2];
            int cc = t & 3;
            float ut = (cc == 0) ? vq.x : (cc == 1) ? vq.y : (cc == 2) ? vq.z : vq.w;
            u64 ut2 = pack2(ut, ut);
            u64 a2  = fma2(P.nwi2, si2, ut2);
            u64 b2  = fma2(P.wr2, si2, mul2(P.wi2, sr2));
            sr2 = fma2(P.wr2, sr2, a2);
            si2 = b2;
            y2[t] = fma2(P.Ccr2, sr2, y2[t]);
            y2[t] = fma2(P.nCci2, si2, y2[t]);
            if (sub == t) uown = ut;
        }
        float a[16];
        #pragma unroll
        for (int t = 0; t < 16; t++) { F2 f; f.u = y2[t]; a[t] = f.f.x + f.f.y; }
        #pragma unroll
        for (int m = 8, cnt = 16; m >= 1; m >>= 1, cnt >>= 1) {
            bool hi = (sub & m) != 0;
            #pragma unroll
            for (int i = 0; i < 8; i++) {
                if (i < cnt / 2) {
                    float send = hi ? a[i] : a[i + cnt / 2];
                    float keep = hi ? a[i + cnt / 2] : a[i];
                    a[i] = keep + __shfl_xor_sync(0xffffffffu, send, m);
                }
            }
        }
        float v   = fmaf(P.Dsk, uown, a[0]);
        float gel = 0.5f * v * (1.0f + erff(v * 0.70710678118654752f));
        __nv_bfloat16 h = __float2bfloat16_rn(gel);
        yhp[c * 16 + sub] = h;
        ylp[c * 16 + sub] = __float2bfloat16_rn(gel - __bfloat162float(h));
        #pragma unroll
        for (int q = 0; q < 4; q++) uv[q] = nv[q];
    }
}

// ================= bf16-split warp-MMA GEMM, 512 thr, fused GLU epilogue ====
// CTA tile: 128 A-rows = a-rows [m0,m0+64) + gate-rows [512+m0,512+m0+64),
// 128 n cols, K32 chunks, double-buffered. 16 warps (2m x 8n), warp tile:
// a-rows wm*32+{0,32} paired with gate rows (mt 0-1 = a, mt 2-3 = gate) so
// z = (a+ba)*sigmoid(g+bg) combines in registers; writes 64MiB z not 128MiB.
#define BKC 32
#define KSTEPS (DM / BKC)    // 16
#define ASTR 144
#define BSTR 272
#define SMA  0
#define SMBH (128 * ASTR)            // 18432
#define SMBL (SMBH + 32 * BSTR)      // 27136
#define SMTOT (SMBL + 32 * BSTR)     // 35840

__global__ __launch_bounds__(512) void gemm_mma_kernel(
    int layer,
    const float* __restrict__ bias)
{
    extern __shared__ __align__(16) char sm[];

    int tid = threadIdx.x;
    int lane = tid & 31, warp = tid >> 5;
    int grp = lane >> 2, tig = lane & 3;
    int wm = warp & 1, wn = warp >> 1;          // 2m x 8n warps
    int m0 = blockIdx.x * 64;                   // a-row base (0..448)
    int n0 = blockIdx.y * 128;
    int bz = blockIdx.z;

    size_t lOff = (size_t)layer * 2 * DM * DM;
    const __nv_bfloat16* yhi_b = g_yhi + (size_t)bz * DM * LL + n0;
    const __nv_bfloat16* ylo_b = g_ylo + (size_t)bz * DM * LL + n0;

    u32 smu = smem_u32(sm);

    float acc[4][2][4];
    #pragma unroll
    for (int i = 0; i < 4; i++)
        #pragma unroll
        for (int j = 0; j < 2; j++)
            #pragma unroll
            for (int q = 0; q < 4; q++) acc[i][j][q] = 0.f;

    // staging roles (512 threads)
    int arow = tid >> 2;            // 0..127 smem A row
    int aseg = tid & 3;             // 16B segment of 64B k-slice
    int gr = (arow < 64) ? (m0 + arow) : (512 + m0 + (arow - 64));
    const __nv_bfloat16* whr = g_whi + lOff + (size_t)gr * DM;
    const __nv_bfloat16* wlr = g_wlo + lOff + (size_t)gr * DM;
    int brow = tid >> 4;            // 0..31 k-row
    int bseg = tid & 15;            // 16B segments across 256B row

    uint4 rAh, rAl, rBh, rBl;

#define GLOAD(k0) do {                                                          \
        rAh = *(const uint4*)(whr + (k0) + aseg * 8);                           \
        rAl = *(const uint4*)(wlr + (k0) + aseg * 8);                           \
        size_t off = (size_t)((k0) + brow) * LL + bseg * 8;                     \
        rBh = *(const uint4*)(yhi_b + off);                                     \
        rBl = *(const uint4*)(ylo_b + off);                                     \
    } while (0)

#define SSTORE(base) do {                                                       \
        *(uint4*)(sm + (base) + SMA + arow * ASTR + aseg * 16) = rAh;           \
        *(uint4*)(sm + (base) + SMA + arow * ASTR + 64 + aseg * 16) = rAl;      \
        *(uint4*)(sm + (base) + SMBH + brow * BSTR + bseg * 16) = rBh;          \
        *(uint4*)(sm + (base) + SMBL + brow * BSTR + bseg * 16) = rBl;          \
    } while (0)

    GLOAD(0);
    SSTORE(0);
    __syncthreads();

    int a_r = lane & 15;
    int a_c = (lane >> 4) << 4;
    int b_r = (lane & 7) + ((lane >> 3) & 1) * 8;
    int b_c = (lane >> 4) << 4;

    for (int c = 0; c < KSTEPS; c++) {
        u32 cur = (u32)(c & 1) * SMTOT;
        if (c + 1 < KSTEPS) GLOAD((c + 1) * BKC);
        #pragma unroll
        for (int kk = 0; kk < 2; kk++) {
            u32 bfh[2][2], bfl[2][2];
            {
                u32 rr[4];
                u32 browl = (u32)(kk * 16 + b_r);
                u32 bcol  = (u32)(wn * 32 + b_c);   // n-base wn*16 * 2 bytes
                ldsm4t(rr, smu + cur + SMBH + browl * BSTR + bcol);
                bfh[0][0] = rr[0]; bfh[0][1] = rr[1];
                bfh[1][0] = rr[2]; bfh[1][1] = rr[3];
                ldsm4t(rr, smu + cur + SMBL + browl * BSTR + bcol);
                bfl[0][0] = rr[0]; bfl[0][1] = rr[1];
                bfl[1][0] = rr[2]; bfl[1][1] = rr[3];
            }
            #pragma unroll
            for (int mt = 0; mt < 4; mt++) {
                u32 af[4], al[4];
                u32 arowl = (u32)(((mt < 2) ? (wm * 32 + mt * 16)
                                            : (64 + wm * 32 + (mt - 2) * 16)) + a_r);
                u32 acol  = (u32)(kk * 32 + a_c);
                ldsm4(af, smu + cur + SMA + arowl * ASTR + acol);
                ldsm4(al, smu + cur + SMA + arowl * ASTR + 64 + acol);
                #pragma unroll
                for (int nt = 0; nt < 2; nt++) {
                    mma16816(acc[mt][nt], af, bfh[nt]);   // hi*hi
                    mma16816(acc[mt][nt], al, bfh[nt]);   // lo*hi
                    mma16816(acc[mt][nt], af, bfl[nt]);   // hi*lo
                }
            }
        }
        if (c + 1 < KSTEPS) {
            SSTORE((u32)((c + 1) & 1) * SMTOT);
            __syncthreads();
        }
    }

    // ---- fused GLU epilogue: z = (a + ba) * sigmoid(g + bg) ----
    float* Pp = g_p + (size_t)bz * DM * LL;
    #pragma unroll
    for (int mt = 0; mt < 2; mt++) {
        int ra = m0 + wm * 32 + mt * 16 + grp;       // a-row global (0..511)
        float ba0 = bias[ra],     bg0 = bias[ra + 512];
        float ba1 = bias[ra + 8], bg1 = bias[ra + 520];
        #pragma unroll
        for (int nt = 0; nt < 2; nt++) {
            const float* A = acc[mt][nt];
            const float* G = acc[mt + 2][nt];
            int col = n0 + wn * 16 + nt * 8 + tig * 2;
            float a0 = A[0] + ba0, a1 = A[1] + ba0;
            float g0 = G[0] + bg0, g1 = G[1] + bg0;
            float2 v0 = { a0 / (1.0f + expf(-g0)), a1 / (1.0f + expf(-g1)) };
            float a2 = A[2] + ba1, a3 = A[3] + ba1;
            float g2 = G[2] + bg1, g3 = G[3] + bg1;
            float2 v1 = { a2 / (1.0f + expf(-g2)), a3 / (1.0f + expf(-g3)) };
            *(float2*)(Pp + (size_t)ra * LL + col) = v0;
            *(float2*)(Pp + (size_t)(ra + 8) * LL + col) = v1;
        }
    }
}

// ================= residual + LayerNorm (z precomputed) =================
__global__ __launch_bounds__(256) void glu_ln_kernel(const float* __restrict__ gam,
                                                     const float* __restrict__ bet)
{
    int lx = threadIdx.x, ty = threadIdx.y;
    int l = blockIdx.x * 32 + lx;
    int b = blockIdx.y;
    __shared__ float R1[8][32], R2[8][32];
    size_t hbase = (size_t)b * DM * LL + l;
    size_t pbase = (size_t)b * DM * LL + l;
    float v[64];
    float s = 0.f, q = 0.f;
    #pragma unroll
    for (int r = 0; r < 64; r++) {
        int d = ty + r * 8;
        float vv = g_h[hbase + (size_t)d * LL] + g_p[pbase + (size_t)d * LL];
        v[r] = vv;
        s += vv; q = fmaf(vv, vv, q);
    }
    R1[ty][lx] = s; R2[ty][lx] = q;
    __syncthreads();
    if (ty == 0) {
        float S = 0.f, Q = 0.f;
        #pragma unroll
        for (int r = 0; r < 8; r++) { S += R1[r][lx]; Q += R2[r][lx]; }
        float mu = S * (1.0f / DM);
        float var = Q * (1.0f / DM) - mu * mu;
        R1[0][lx] = mu;
        R2[0][lx] = rsqrtf(var + 1e-5f);
    }
    __syncthreads();
    float mu = R1[0][lx], rs = R2[0][lx];
    #pragma unroll
    for (int r = 0; r < 64; r++) {
        int d = ty + r * 8;
        g_h[hbase + (size_t)d * LL] = (v[r] - mu) * rs * gam[d] + bet[d];
    }
}

// ================= mean over L =================
__global__ void mean_kernel()
{
    int row = blockIdx.x;
    size_t base = (size_t)row * LL;
    float s = 0.f;
    for (int l = threadIdx.x; l < LL; l += 128) s += g_h[base + l];
    #pragma unroll
    for (int o = 16; o; o >>= 1) s += __shfl_xor_sync(0xffffffffu, s, o);
    __shared__ float sm[4];
    int wid = threadIdx.x >> 5;
    if ((threadIdx.x & 31) == 0) sm[wid] = s;
    __syncthreads();
    if (threadIdx.x == 0)
        g_hm[row] = (sm[0] + sm[1] + sm[2] + sm[3]) * (1.0f / LL);
}

// ================= stats head =================
__global__ void stats_kernel(const float* __restrict__ Ws,
                             const float* __restrict__ bs,
                             float* __restrict__ out)
{
    int w = (blockIdx.x * blockDim.x + threadIdx.x) >> 5;
    int lane = threadIdx.x & 31;
    int b = w >> 9;
    int o = w & 511;
    const float* hm = g_hm + b * DM;
    const float* wrow = Ws + (size_t)o * DM;
    float s = 0.f;
    for (int d = lane; d < DM; d += 32) s = fmaf(wrow[d], hm[d], s);
    #pragma unroll
    for (int off = 16; off; off >>= 1) s += __shfl_xor_sync(0xffffffffu, s, off);
    if (lane == 0) {
        float v = s + bs[o];
        if (o < 256) out[b * 256 + o] = v;
        else         out[2048 + b * 256 + (o - 256)] = v;
    }
}

// ================= launch =================
extern "C" void kernel_launch(void* const* d_in, const int* in_sizes, int n_in,
                              void* d_out, int out_size)
{
    const float* x      = (const float*)d_in[0];
    const float* Wproj  = (const float*)d_in[1];
    const float* bproj  = (const float*)d_in[2];
    const float* pos    = (const float*)d_in[3];
    const float* log_dt = (const float*)d_in[4];
    const float* logAre = (const float*)d_in[5];
    const float* Aim    = (const float*)d_in[6];
    const float* Cre    = (const float*)d_in[7];
    const float* Cim    = (const float*)d_in[8];
    const float* Dsk    = (const float*)d_in[9];
    const float* Wout   = (const float*)d_in[10];
    const float* bout   = (const float*)d_in[11];
    const float* lng    = (const float*)d_in[12];
    const float* lnb    = (const float*)d_in[13];
    const float* Wstats = (const float*)d_in[14];
    const float* bstats = (const float*)d_in[15];
    float* out = (float*)d_out;

    cudaFuncSetAttribute(gemm_mma_kernel,
                         cudaFuncAttributeMaxDynamicSharedMemorySize, 2 * SMTOT);

    wsplit_kernel<<<4 * 2 * DM * DM / 256, 256>>>(Wout);
    proj_kernel<<<dim3(LL / 32, DM / 32, BB), dim3(32, 8)>>>(x, Wproj, bproj, pos);

    for (int layer = 0; layer < 4; ++layer) {
        const float* ld = log_dt + layer * DM;
        const float* la = logAre + (size_t)layer * DM * N2C;
        const float* ai = Aim    + (size_t)layer * DM * N2C;
        ssm_pass1<<<dim3(512, NSEG - 1), 128>>>(ld, la, ai);
        ssm_combine<<<BB * DM * N2C / 256, 256>>>(ld, la, ai);
        ssm_pass2<<<dim3(512, NSEG), 128>>>(ld, la, ai,
                                            Cre + (size_t)layer * DM * N2C,
                                            Cim + (size_t)layer * DM * N2C,
                                            Dsk + layer * DM);
        gemm_mma_kernel<<<dim3(DM / 64, LL / 128, BB), 512, 2 * SMTOT>>>(
            layer, bout + layer * 2 * DM);
        glu_ln_kernel<<<dim3(LL / 32, BB), dim3(32, 8)>>>(lng + layer * DM,
                                                          lnb + layer * DM);
    }

    mean_kernel<<<BB * DM, 128>>>();
    stats_kernel<<<512, 256>>>(Wstats, bstats, out);
}